// round 14
// baseline (speedup 1.0000x reference)
#include <cuda_runtime.h>
#include <cuda_bf16.h>
#include <cuda_fp16.h>
#include <cstdint>
#include <cstddef>

#define BATCH 4
#define MDIM  4096
#define NDIM  4096
#define DQK   256

static constexpr float LOG2E = 1.4426950408889634f;

// ---------------------------------------------------------------------------
// helpers
// ---------------------------------------------------------------------------
__device__ __forceinline__ uint32_t smem_u32(const void* p) {
    uint32_t a;
    asm("{ .reg .u64 t; cvta.to.shared.u64 t, %1; cvt.u32.u64 %0, t; }"
        : "=r"(a) : "l"(p));
    return a;
}

__device__ __forceinline__ float ex2f(float x) {
    float r; asm("ex2.approx.ftz.f32 %0, %1;" : "=f"(r) : "f"(x)); return r;
}

__device__ __forceinline__ uint32_t pack_h2(float a, float b) {
    __half2 h = __floats2half2_rn(a, b);
    return *reinterpret_cast<uint32_t*>(&h);
}

#define LDSM_X4(r0, r1, r2, r3, a) \
    asm volatile("ldmatrix.sync.aligned.m8n8.x4.shared.b16 {%0,%1,%2,%3}, [%4];" \
                 : "=r"(r0), "=r"(r1), "=r"(r2), "=r"(r3) : "r"(a))

#define LDSM_X4T(r0, r1, r2, r3, a) \
    asm volatile("ldmatrix.sync.aligned.m8n8.x4.trans.shared.b16 {%0,%1,%2,%3}, [%4];" \
                 : "=r"(r0), "=r"(r1), "=r"(r2), "=r"(r3) : "r"(a))

#define MMA_F16(d, a0, a1, a2, a3, b0, b1)                                     \
    asm volatile("mma.sync.aligned.m16n8k16.row.col.f32.f16.f16.f32 "          \
                 "{%0,%1,%2,%3}, {%4,%5,%6,%7}, {%8,%9}, {%0,%1,%2,%3};"       \
                 : "+f"((d)[0]), "+f"((d)[1]), "+f"((d)[2]), "+f"((d)[3])      \
                 : "r"(a0), "r"(a1), "r"(a2), "r"(a3), "r"(b0), "r"(b1))

#define CP_ASYNC16(dst, src) \
    asm volatile("cp.async.cg.shared.global [%0], [%1], 16;" \
                 :: "r"(dst), "l"(src) : "memory")
#define CP_COMMIT() asm volatile("cp.async.commit_group;" ::: "memory")
#define CP_WAIT0()  asm volatile("cp.async.wait_group 0;" ::: "memory")
#define CP_WAIT1()  asm volatile("cp.async.wait_group 1;" ::: "memory")
#define CP_WAIT2()  asm volatile("cp.async.wait_group 2;" ::: "memory")

// ---------------------------------------------------------------------------
// scratch: fp16 Q(scaled by 0.125*log2e), K, V — row-major [b*4096+row][64]
// ---------------------------------------------------------------------------
__device__ __half g_q[(size_t)BATCH * MDIM * 64];
__device__ __half g_k[(size_t)BATCH * NDIM * 64];
__device__ __half g_v[(size_t)BATCH * NDIM * 64];

// ---------------------------------------------------------------------------
// Projection body (R12 kv_proj recipe): 64 rows/CTA, 128 threads (4 warps),
// cp.async double-buffered A staging, per-chunk W16 staging.
// C[64 x NC] = A[64 x 256] @ W[256 x NC].
// smem: A16 @0 (8KB), W16 @8K (<=16KB), A32 stages @24K (2 x 16KB) = 56KB.
// MODE 0 (NC=64): scale 0.125*LOG2E -> o0 (Q).
// MODE 1 (NC=128): cols<64 -> o0 (K), else o1 (V).
// ---------------------------------------------------------------------------
template <int NC, int MODE>
__device__ __forceinline__ void proj_body(
    char* sm, const float* __restrict__ A, const float* __restrict__ W,
    __half* __restrict__ o0, __half* __restrict__ o1, int bi)
{
    const uint32_t sb = smem_u32(sm);
    constexpr uint32_t OFF_W   = 8192;
    constexpr uint32_t OFF_A32 = 24576;

    const int t = threadIdx.x, w = t >> 5, lane = t & 31;
    const int mat = lane >> 3, r = lane & 7;
    const int g = lane >> 2, q4 = lane & 3;
    const int r0 = bi * 64;

    float acc[NC / 8][4];
#pragma unroll
    for (int j = 0; j < NC / 8; j++)
#pragma unroll
        for (int i = 0; i < 4; i++) acc[j][i] = 0.f;

    auto issueA = [&](int kc, uint32_t stage) {
        const float* src = A + (size_t)r0 * DQK + kc * 64;
#pragma unroll
        for (int i = t; i < 1024; i += 128) {
            int row = i >> 4, c4 = i & 15;
            CP_ASYNC16(sb + OFF_A32 + stage * 16384u + (uint32_t)i * 16u,
                       src + (size_t)row * DQK + c4 * 4);
        }
    };

    issueA(0, 0); CP_COMMIT();
    issueA(1, 1); CP_COMMIT();

    for (int kc = 0; kc < 4; kc++) {
        if (kc) __syncthreads();

        // W chunk [64 x NC] fp32 -> fp16
#pragma unroll
        for (int i = t; i < 16 * NC; i += 128) {
            int kr = i / (NC / 4), c4 = i % (NC / 4);
            float4 v = *(const float4*)(W + (size_t)(kc * 64 + kr) * NC + c4 * 4);
            uint32_t h0 = pack_h2(v.x, v.y);
            uint32_t h1 = pack_h2(v.z, v.w);
            uint32_t bc = (uint32_t)(c4 * 8);
            uint32_t off = (uint32_t)(kr * NC * 2) + (bc & ~127u)
                         + ((bc & 127u) ^ (uint32_t)((kr & 7) << 4));
            *(uint2*)(sm + OFF_W + off) = make_uint2(h0, h1);
        }

        if (kc == 3) { CP_WAIT0(); } else { CP_WAIT1(); }
        const uint32_t stg = OFF_A32 + (uint32_t)(kc & 1) * 16384u;
#pragma unroll
        for (int i = t; i < 1024; i += 128) {
            int row = i >> 4, c4 = i & 15;
            float4 v = *(const float4*)(sm + stg + (uint32_t)i * 16u);
            uint32_t h0 = pack_h2(v.x, v.y);
            uint32_t h1 = pack_h2(v.z, v.w);
            uint32_t off = (uint32_t)(row * 128) + (uint32_t)((c4 * 8) ^ ((row & 7) << 4));
            *(uint2*)(sm + off) = make_uint2(h0, h1);
        }
        __syncthreads();

        if (kc + 2 < 4) { issueA(kc + 2, (uint32_t)(kc & 1)); }
        CP_COMMIT();

        uint32_t ah[4][4];
#pragma unroll
        for (int kf = 0; kf < 4; kf++) {
            uint32_t off = (uint32_t)((w * 16 + (mat & 1) * 8 + r) * 128)
                         + (uint32_t)((kf * 32 + (mat >> 1) * 16) ^ (r << 4));
            LDSM_X4(ah[kf][0], ah[kf][1], ah[kf][2], ah[kf][3], sb + off);
        }
#pragma unroll
        for (int np = 0; np < NC / 16; np++) {
#pragma unroll
            for (int kf = 0; kf < 4; kf++) {
                int krow = kf * 16 + (mat & 1) * 8 + r;
                uint32_t bc = (uint32_t)(np * 32 + (mat >> 1) * 16);
                uint32_t off = (uint32_t)(krow * NC * 2) + (bc & ~127u)
                             + ((bc & 127u) ^ (uint32_t)((krow & 7) << 4));
                uint32_t b0, b1, b2, b3;
                LDSM_X4T(b0, b1, b2, b3, sm != nullptr ? sb + OFF_W + off : 0u);
                MMA_F16(acc[2 * np],     ah[kf][0], ah[kf][1], ah[kf][2], ah[kf][3], b0, b1);
                MMA_F16(acc[2 * np + 1], ah[kf][0], ah[kf][1], ah[kf][2], ah[kf][3], b2, b3);
            }
        }
    }

    const float sc = (MODE == 0) ? 0.125f * LOG2E : 1.f;
    const int row = r0 + w * 16 + g;
#pragma unroll
    for (int j = 0; j < NC / 8; j++) {
        uint32_t p01 = pack_h2(acc[j][0] * sc, acc[j][1] * sc);
        uint32_t p23 = pack_h2(acc[j][2] * sc, acc[j][3] * sc);
        int col = j * 8 + q4 * 2;
        __half* dst = o0;
        int cc = col;
        if (MODE == 1 && col >= 64) { dst = o1; cc = col - 64; }
        *(uint32_t*)(dst + (size_t)row * 64 + cc)       = p01;
        *(uint32_t*)(dst + (size_t)(row + 8) * 64 + cc) = p23;
    }
}

// One launch: blocks [0,256) KV (NC=128), [256,512) Q (NC=64).
__global__ void __launch_bounds__(128, 2) proj_all(
    const float* __restrict__ x,    const float* __restrict__ Wq,
    const float* __restrict__ cond, const float* __restrict__ Wkv,
    __half* __restrict__ q, __half* __restrict__ k, __half* __restrict__ v)
{
    extern __shared__ char sm[];
    if (blockIdx.x < 256) proj_body<128, 1>(sm, cond, Wkv, k, v, blockIdx.x);
    else                  proj_body<64, 0>(sm, x, Wq, q, nullptr, blockIdx.x - 256);
}

// ---------------------------------------------------------------------------
// Attention (fp16): identical to R10/R11 best (51.5us). 1 CTA = 64 q-rows,
// 4 warps 2x2 (mw x kw), 2 CTAs/SM, 3-stage cp.async ring, PV one key-group
// behind S/exp. Q pre-scaled by 0.125*log2e (exp2 domain).
// ---------------------------------------------------------------------------
__device__ __forceinline__ void issue_tile(
    uint32_t sb, uint32_t buf, int nt, int t,
    const uint4* k4, const uint4* v4)
{
    const uint4* k = k4 + nt * 1024;
    const uint4* v = v4 + nt * 1024;
#pragma unroll
    for (int i = t; i < 1024; i += 128) {
        int row = i >> 3, c = i & 7;
        uint32_t off = buf + (uint32_t)(row * 128)
                     + (uint32_t)((c * 16) ^ ((row & 7) << 4));
        CP_ASYNC16(sb + off,         k + i);
        CP_ASYNC16(sb + off + 16384, v + i);
    }
}

__global__ void __launch_bounds__(128, 2) attn_kernel(
    const __half* __restrict__ Q, const __half* __restrict__ K,
    const __half* __restrict__ V, float* __restrict__ O)
{
    extern __shared__ char smem[];
    const uint32_t sb = smem_u32(smem);

    const int t    = threadIdx.x;
    const int w    = t >> 5, lane = t & 31;
    const int mw   = w >> 1, kw = w & 1;
    const int g    = lane >> 2, q4 = lane & 3;
    const int mat  = lane >> 3, r = lane & 7;
    const int bb   = blockIdx.y;
    const int m0   = blockIdx.x * 64;

    {
        const uint4* q4p = (const uint4*)(Q + ((size_t)(bb * MDIM + m0)) * 64);
#pragma unroll
        for (int i = t; i < 512; i += 128) {
            int row = i >> 3, c = i & 7;
            uint32_t off = (uint32_t)(row * 128) + (uint32_t)((c * 16) ^ ((row & 7) << 4));
            *(uint4*)(smem + off) = q4p[i];
        }
    }
    __syncthreads();

    uint32_t qh[2][4][4];
#pragma unroll
    for (int mt = 0; mt < 2; mt++)
#pragma unroll
        for (int kf = 0; kf < 4; kf++) {
            uint32_t off = (uint32_t)((mw * 32 + mt * 16 + (mat & 1) * 8 + r) * 128)
                         + (uint32_t)((kf * 32 + (mat >> 1) * 16) ^ (r << 4));
            LDSM_X4(qh[mt][kf][0], qh[mt][kf][1], qh[mt][kf][2], qh[mt][kf][3],
                    sb + off);
        }
    __syncthreads();

    float oacc[2][8][4];
#pragma unroll
    for (int mt = 0; mt < 2; mt++)
#pragma unroll
        for (int n = 0; n < 8; n++)
#pragma unroll
            for (int j = 0; j < 4; j++) oacc[mt][n][j] = 0.f;
    float ll[2][2] = {{0.f, 0.f}, {0.f, 0.f}};

    const uint4* k4 = (const uint4*)(K + (size_t)(bb * NDIM) * 64);
    const uint4* v4 = (const uint4*)(V + (size_t)(bb * NDIM) * 64);

    issue_tile(sb, 0,     0, t, k4, v4); CP_COMMIT();
    issue_tile(sb, 32768, 1, t, k4, v4); CP_COMMIT();
    issue_tile(sb, 65536, 2, t, k4, v4); CP_COMMIT();

    for (int nt = 0; nt < NDIM / 128; ++nt) {
        CP_WAIT2();
        __syncthreads();
        const uint32_t buf = (uint32_t)(nt % 3) * 32768u;

        uint32_t pa[2][4];
        uint32_t vb[4][4];

#pragma unroll
        for (int tp = 0; tp < 5; tp++) {
            if (tp > 0) {
                const int kgp = kw * 4 + tp - 1;
                const uint32_t rowa = (uint32_t)((kgp * 16 + (mat & 1) * 8 + r) * 128);
#pragma unroll
                for (int hp = 0; hp < 4; hp++) {
                    uint32_t av = sb + buf + 16384 + rowa
                                + (uint32_t)((hp * 32 + (mat >> 1) * 16) ^ (r << 4));
                    LDSM_X4T(vb[hp][0], vb[hp][1], vb[hp][2], vb[hp][3], av);
                }
            }

            uint32_t kb[4][4];
            if (tp < 4) {
                const int kg = kw * 4 + tp;
                const uint32_t rowb = (uint32_t)((kg * 16 + (mat >> 1) * 8 + r) * 128);
#pragma unroll
                for (int kf = 0; kf < 4; kf++) {
                    uint32_t a = sb + buf + rowb
                               + (uint32_t)((kf * 32 + (mat & 1) * 16) ^ (r << 4));
                    LDSM_X4(kb[kf][0], kb[kf][1], kb[kf][2], kb[kf][3], a);
                }
            }

            if (tp > 0) {
#pragma unroll
                for (int hp = 0; hp < 4; hp++)
#pragma unroll
                    for (int mt = 0; mt < 2; mt++) {
                        MMA_F16(oacc[mt][2 * hp],     pa[mt][0], pa[mt][1],
                                pa[mt][2], pa[mt][3], vb[hp][0], vb[hp][1]);
                        MMA_F16(oacc[mt][2 * hp + 1], pa[mt][0], pa[mt][1],
                                pa[mt][2], pa[mt][3], vb[hp][2], vb[hp][3]);
                    }
            }

            if (tp < 4) {
                float s[2][2][4];
#pragma unroll
                for (int mt = 0; mt < 2; mt++) {
#pragma unroll
                    for (int nb = 0; nb < 2; nb++)
#pragma unroll
                        for (int j = 0; j < 4; j++) s[mt][nb][j] = 0.f;
#pragma unroll
                    for (int kf = 0; kf < 4; kf++) {
                        MMA_F16(s[mt][0], qh[mt][kf][0], qh[mt][kf][1],
                                qh[mt][kf][2], qh[mt][kf][3], kb[kf][0], kb[kf][1]);
                        MMA_F16(s[mt][1], qh[mt][kf][0], qh[mt][kf][1],
                                qh[mt][kf][2], qh[mt][kf][3], kb[kf][2], kb[kf][3]);
                    }
                }
#pragma unroll
                for (int mt = 0; mt < 2; mt++) {
                    float e00 = ex2f(s[mt][0][0]), e01 = ex2f(s[mt][0][1]);
                    float e02 = ex2f(s[mt][0][2]), e03 = ex2f(s[mt][0][3]);
                    float e10 = ex2f(s[mt][1][0]), e11 = ex2f(s[mt][1][1]);
                    float e12 = ex2f(s[mt][1][2]), e13 = ex2f(s[mt][1][3]);
                    ll[mt][0] += e00 + e01 + e10 + e11;
                    ll[mt][1] += e02 + e03 + e12 + e13;
                    pa[mt][0] = pack_h2(e00, e01); pa[mt][1] = pack_h2(e02, e03);
                    pa[mt][2] = pack_h2(e10, e11); pa[mt][3] = pack_h2(e12, e13);
                }
            }
        }

        __syncthreads();
        if (nt + 3 < NDIM / 128)
            issue_tile(sb, buf, nt + 3, t, k4, v4);
        CP_COMMIT();
    }

#pragma unroll
    for (int mt = 0; mt < 2; mt++)
#pragma unroll
        for (int h = 0; h < 2; h++) {
            ll[mt][h] += __shfl_xor_sync(0xffffffffu, ll[mt][h], 1);
            ll[mt][h] += __shfl_xor_sync(0xffffffffu, ll[mt][h], 2);
        }

    __syncthreads();
    float* Osm = (float*)smem;             // [64 rows][64 cols]
    float* lsm = (float*)(smem + 16384);   // [64 rows]

    if (kw == 1) {
#pragma unroll
        for (int mt = 0; mt < 2; mt++) {
            int rr = mw * 32 + mt * 16 + g;
            float* d0 = Osm + rr * 64;
            float* d1 = d0 + 8 * 64;
#pragma unroll
            for (int n = 0; n < 8; n++) {
                int col = n * 8 + q4 * 2;
                *(float2*)(d0 + col) = make_float2(oacc[mt][n][0], oacc[mt][n][1]);
                *(float2*)(d1 + col) = make_float2(oacc[mt][n][2], oacc[mt][n][3]);
            }
            if (q4 == 0) {
                lsm[rr]     = ll[mt][0];
                lsm[rr + 8] = ll[mt][1];
            }
        }
    }
    __syncthreads();

    if (kw == 0) {
#pragma unroll
        for (int mt = 0; mt < 2; mt++) {
            int rr = mw * 32 + mt * 16 + g;
            const float* s0 = Osm + rr * 64;
            const float* s1 = s0 + 8 * 64;
            const float i0 = 1.f / (ll[mt][0] + lsm[rr]);
            const float i1 = 1.f / (ll[mt][1] + lsm[rr + 8]);
            float* Og0 = O + ((size_t)(bb * MDIM + m0 + rr)) * 64;
            float* Og1 = Og0 + 8 * 64;
#pragma unroll
            for (int n = 0; n < 8; n++) {
                int col = n * 8 + q4 * 2;
                float2 a0 = *(const float2*)(s0 + col);
                float2 a1 = *(const float2*)(s1 + col);
                *(float2*)(Og0 + col) = make_float2((oacc[mt][n][0] + a0.x) * i0,
                                                    (oacc[mt][n][1] + a0.y) * i0);
                *(float2*)(Og1 + col) = make_float2((oacc[mt][n][2] + a1.x) * i1,
                                                    (oacc[mt][n][3] + a1.y) * i1);
            }
        }
    }
}

// ---------------------------------------------------------------------------
// Launch
// ---------------------------------------------------------------------------
extern "C" void kernel_launch(void* const* d_in, const int* in_sizes, int n_in,
                              void* d_out, int out_size)
{
    const float* x    = (const float*)d_in[0];
    const float* cond = (const float*)d_in[1];
    const float* Wq   = (const float*)d_in[2];
    const float* Wkv  = (const float*)d_in[3];
    float* out = (float*)d_out;

    __half *q, *k, *v;
    cudaGetSymbolAddress((void**)&q, g_q);
    cudaGetSymbolAddress((void**)&k, g_k);
    cudaGetSymbolAddress((void**)&v, g_v);

    cudaFuncSetAttribute(proj_all,
                         cudaFuncAttributeMaxDynamicSharedMemorySize, 57344);
    cudaFuncSetAttribute(attn_kernel,
                         cudaFuncAttributeMaxDynamicSharedMemorySize, 98304);

    proj_all<<<512, 128, 57344>>>(x, Wq, cond, Wkv, q, k, v);

    dim3 grid(MDIM / 64, BATCH);
    attn_kernel<<<grid, 128, 98304>>>(q, k, v, out);
}

// round 15
// speedup vs baseline: 1.0884x; 1.0884x over previous
#include <cuda_runtime.h>
#include <cuda_bf16.h>
#include <cuda_fp16.h>
#include <cstdint>
#include <cstddef>

#define BATCH 4
#define MDIM  4096
#define NDIM  4096
#define DQK   256

static constexpr float LOG2E = 1.4426950408889634f;

// ---------------------------------------------------------------------------
// helpers
// ---------------------------------------------------------------------------
__device__ __forceinline__ uint32_t smem_u32(const void* p) {
    uint32_t a;
    asm("{ .reg .u64 t; cvta.to.shared.u64 t, %1; cvt.u32.u64 %0, t; }"
        : "=r"(a) : "l"(p));
    return a;
}

__device__ __forceinline__ float ex2f(float x) {
    float r; asm("ex2.approx.ftz.f32 %0, %1;" : "=f"(r) : "f"(x)); return r;
}

__device__ __forceinline__ uint32_t pack_h2(float a, float b) {
    __half2 h = __floats2half2_rn(a, b);
    return *reinterpret_cast<uint32_t*>(&h);
}

#define LDSM_X4(r0, r1, r2, r3, a) \
    asm volatile("ldmatrix.sync.aligned.m8n8.x4.shared.b16 {%0,%1,%2,%3}, [%4];" \
                 : "=r"(r0), "=r"(r1), "=r"(r2), "=r"(r3) : "r"(a))

#define LDSM_X4T(r0, r1, r2, r3, a) \
    asm volatile("ldmatrix.sync.aligned.m8n8.x4.trans.shared.b16 {%0,%1,%2,%3}, [%4];" \
                 : "=r"(r0), "=r"(r1), "=r"(r2), "=r"(r3) : "r"(a))

#define MMA_F16(d, a0, a1, a2, a3, b0, b1)                                     \
    asm volatile("mma.sync.aligned.m16n8k16.row.col.f32.f16.f16.f32 "          \
                 "{%0,%1,%2,%3}, {%4,%5,%6,%7}, {%8,%9}, {%0,%1,%2,%3};"       \
                 : "+f"((d)[0]), "+f"((d)[1]), "+f"((d)[2]), "+f"((d)[3])      \
                 : "r"(a0), "r"(a1), "r"(a2), "r"(a3), "r"(b0), "r"(b1))

#define CP_ASYNC16(dst, src) \
    asm volatile("cp.async.cg.shared.global [%0], [%1], 16;" \
                 :: "r"(dst), "l"(src) : "memory")
#define CP_COMMIT() asm volatile("cp.async.commit_group;" ::: "memory")
#define CP_WAIT0()  asm volatile("cp.async.wait_group 0;" ::: "memory")
#define CP_WAIT1()  asm volatile("cp.async.wait_group 1;" ::: "memory")
#define CP_WAIT2()  asm volatile("cp.async.wait_group 2;" ::: "memory")

// ---------------------------------------------------------------------------
// scratch: fp16 K, V — row-major [b*4096+n][64]
// ---------------------------------------------------------------------------
__device__ __half g_k[(size_t)BATCH * NDIM * 64];
__device__ __half g_v[(size_t)BATCH * NDIM * 64];

// ---------------------------------------------------------------------------
// KV projection (R12 version verbatim — measured 8.3us):
// 64 rows/CTA, 128 threads (4 warps x 16 rows), grid 256.
// cp.async double-buffered A staging, per-chunk W16 staging.
// smem: A16 @0 (8KB), W16 @8K (16KB), A32 stages @24K (2 x 16KB) = 56KB.
// ---------------------------------------------------------------------------
__global__ void __launch_bounds__(128, 2) kv_proj(
    const float* __restrict__ A, const float* __restrict__ W,
    __half* __restrict__ ko, __half* __restrict__ vo)
{
    extern __shared__ char sm[];
    const uint32_t sb = smem_u32(sm);
    constexpr uint32_t OFF_W   = 8192;
    constexpr uint32_t OFF_A32 = 24576;

    const int t = threadIdx.x, w = t >> 5, lane = t & 31;
    const int mat = lane >> 3, r = lane & 7;
    const int g = lane >> 2, q4 = lane & 3;
    const int r0 = blockIdx.x * 64;

    float acc[16][4];
#pragma unroll
    for (int j = 0; j < 16; j++)
#pragma unroll
        for (int i = 0; i < 4; i++) acc[j][i] = 0.f;

    auto issueA = [&](int kc, uint32_t stage) {
        const float* src = A + (size_t)r0 * DQK + kc * 64;
#pragma unroll
        for (int i = t; i < 1024; i += 128) {
            int row = i >> 4, c4 = i & 15;
            CP_ASYNC16(sb + OFF_A32 + stage * 16384u + (uint32_t)i * 16u,
                       src + (size_t)row * DQK + c4 * 4);
        }
    };

    issueA(0, 0); CP_COMMIT();
    issueA(1, 1); CP_COMMIT();

    for (int kc = 0; kc < 4; kc++) {
        if (kc) __syncthreads();

        // W chunk [64 x 128] fp32 -> fp16
#pragma unroll
        for (int i = t; i < 2048; i += 128) {
            int kr = i >> 5, c4 = i & 31;
            float4 v = *(const float4*)(W + (size_t)(kc * 64 + kr) * 128 + c4 * 4);
            uint32_t h0 = pack_h2(v.x, v.y);
            uint32_t h1 = pack_h2(v.z, v.w);
            uint32_t bc = (uint32_t)(c4 * 8);
            uint32_t off = (uint32_t)(kr * 256) + (bc & ~127u)
                         + ((bc & 127u) ^ (uint32_t)((kr & 7) << 4));
            *(uint2*)(sm + OFF_W + off) = make_uint2(h0, h1);
        }

        if (kc == 3) { CP_WAIT0(); } else { CP_WAIT1(); }
        const uint32_t stg = OFF_A32 + (uint32_t)(kc & 1) * 16384u;
#pragma unroll
        for (int i = t; i < 1024; i += 128) {
            int row = i >> 4, c4 = i & 15;
            float4 v = *(const float4*)(sm + stg + (uint32_t)i * 16u);
            uint32_t h0 = pack_h2(v.x, v.y);
            uint32_t h1 = pack_h2(v.z, v.w);
            uint32_t off = (uint32_t)(row * 128) + (uint32_t)((c4 * 8) ^ ((row & 7) << 4));
            *(uint2*)(sm + off) = make_uint2(h0, h1);
        }
        __syncthreads();

        if (kc + 2 < 4) { issueA(kc + 2, (uint32_t)(kc & 1)); }
        CP_COMMIT();

        uint32_t ah[4][4];
#pragma unroll
        for (int kf = 0; kf < 4; kf++) {
            uint32_t off = (uint32_t)((w * 16 + (mat & 1) * 8 + r) * 128)
                         + (uint32_t)((kf * 32 + (mat >> 1) * 16) ^ (r << 4));
            LDSM_X4(ah[kf][0], ah[kf][1], ah[kf][2], ah[kf][3], sb + off);
        }
#pragma unroll
        for (int np = 0; np < 8; np++) {
#pragma unroll
            for (int kf = 0; kf < 4; kf++) {
                int krow = kf * 16 + (mat & 1) * 8 + r;
                uint32_t bc = (uint32_t)(np * 32 + (mat >> 1) * 16);
                uint32_t off = (uint32_t)(krow * 256) + (bc & ~127u)
                             + ((bc & 127u) ^ (uint32_t)((krow & 7) << 4));
                uint32_t b0, b1, b2, b3;
                LDSM_X4T(b0, b1, b2, b3, sb + OFF_W + off);
                MMA_F16(acc[2 * np],     ah[kf][0], ah[kf][1], ah[kf][2], ah[kf][3], b0, b1);
                MMA_F16(acc[2 * np + 1], ah[kf][0], ah[kf][1], ah[kf][2], ah[kf][3], b2, b3);
            }
        }
    }

    const int row = r0 + w * 16 + g;
#pragma unroll
    for (int j = 0; j < 16; j++) {
        uint32_t p01 = pack_h2(acc[j][0], acc[j][1]);
        uint32_t p23 = pack_h2(acc[j][2], acc[j][3]);
        int col = j * 8 + q4 * 2;
        __half* dst = (col < 64) ? ko : vo;
        int cc = (col < 64) ? col : col - 64;
        *(uint32_t*)(dst + (size_t)row * 64 + cc)       = p01;
        *(uint32_t*)(dst + (size_t)(row + 8) * 64 + cc) = p23;
    }
}

// ---------------------------------------------------------------------------
// Attention (fp16) with cp.async-pipelined fused Q projection.
// Prologue: x chunks cp.async double-buffered (fp32 stages, 272B padded rows);
// A-frags packed straight from fp32 stage (no LDSM for A, no x16 pass);
// Wq16 staged ONCE @64K. Mainloop identical to R11 best (51.5us).
// ---------------------------------------------------------------------------
__device__ __forceinline__ void issue_tile(
    uint32_t sb, uint32_t buf, int nt, int t,
    const uint4* k4, const uint4* v4)
{
    const uint4* k = k4 + nt * 1024;
    const uint4* v = v4 + nt * 1024;
#pragma unroll
    for (int i = t; i < 1024; i += 128) {
        int row = i >> 3, c = i & 7;
        uint32_t off = buf + (uint32_t)(row * 128)
                     + (uint32_t)((c * 16) ^ ((row & 7) << 4));
        CP_ASYNC16(sb + off,         k + i);
        CP_ASYNC16(sb + off + 16384, v + i);
    }
}

__global__ void __launch_bounds__(128, 2) attn_kernel(
    const float* __restrict__ X, const float* __restrict__ Wq,
    const __half* __restrict__ K, const __half* __restrict__ V,
    float* __restrict__ O)
{
    extern __shared__ char smem[];
    const uint32_t sb = smem_u32(smem);

    const int t    = threadIdx.x;
    const int w    = t >> 5, lane = t & 31;
    const int mw   = w >> 1, kw = w & 1;
    const int g    = lane >> 2, q4 = lane & 3;
    const int mat  = lane >> 3, r = lane & 7;
    const int bb   = blockIdx.y;
    const int m0   = blockIdx.x * 64;

    // ================= Q-projection prologue (cp.async pipelined) ==========
    uint32_t qh[2][4][4];
    {
        constexpr uint32_t XS0    = 0;       // fp32 x stage 0 (64 x 272 B)
        constexpr uint32_t XS1    = 20480;   // fp32 x stage 1
        constexpr uint32_t OFF_WQ = 65536;   // Wq16, 16 KB

        const float* Xb = X + (size_t)(bb * MDIM + m0) * DQK;

        auto issueX = [&](int kc, uint32_t stage) {
            const float* src = Xb + kc * 64;
#pragma unroll
            for (int i = t; i < 1024; i += 128) {
                int row = i >> 4, c4 = i & 15;
                CP_ASYNC16(sb + stage + (uint32_t)(row * 272 + c4 * 16),
                           src + (size_t)row * DQK + c4 * 4);
            }
        };

        issueX(0, XS0); CP_COMMIT();
        issueX(1, XS1); CP_COMMIT();

        // stage Wq16 once: 256 rows x 128 B, swizzled
#pragma unroll 4
        for (int i = t; i < 4096; i += 128) {
            int kr = i >> 4, c4 = i & 15;
            float4 v = *(const float4*)(Wq + (size_t)kr * 64 + c4 * 4);
            uint32_t h0 = pack_h2(v.x, v.y);
            uint32_t h1 = pack_h2(v.z, v.w);
            uint32_t bc = (uint32_t)(c4 * 8);
            uint32_t off = (uint32_t)(kr * 128) + (bc ^ (uint32_t)((kr & 7) << 4));
            *(uint2*)(smem + OFF_WQ + off) = make_uint2(h0, h1);
        }

        float qacc[2][8][4];
#pragma unroll
        for (int mt = 0; mt < 2; mt++)
#pragma unroll
            for (int j = 0; j < 8; j++)
#pragma unroll
                for (int i = 0; i < 4; i++) qacc[mt][j][i] = 0.f;

        for (int kc = 0; kc < 4; kc++) {
            if (kc == 3) { CP_WAIT0(); } else { CP_WAIT1(); }
            __syncthreads();   // x stage + (kc==0) Wq visible to all

            const uint32_t xs = (kc & 1) ? XS1 : XS0;
            uint32_t ax[2][4][4];
#pragma unroll
            for (int mt = 0; mt < 2; mt++) {
                const int row  = mw * 32 + mt * 16 + g;
#pragma unroll
                for (int kf = 0; kf < 4; kf++) {
                    const uint32_t c0 = (uint32_t)((kf * 16 + q4 * 2) * 4);
                    float2 v0 = *(const float2*)(smem + xs + row * 272 + c0);
                    float2 v1 = *(const float2*)(smem + xs + (row + 8) * 272 + c0);
                    float2 v2 = *(const float2*)(smem + xs + row * 272 + c0 + 32);
                    float2 v3 = *(const float2*)(smem + xs + (row + 8) * 272 + c0 + 32);
                    ax[mt][kf][0] = pack_h2(v0.x, v0.y);
                    ax[mt][kf][1] = pack_h2(v1.x, v1.y);
                    ax[mt][kf][2] = pack_h2(v2.x, v2.y);
                    ax[mt][kf][3] = pack_h2(v3.x, v3.y);
                }
            }
            __syncthreads();   // all reads of this stage done before refill
            if (kc + 2 < 4) { issueX(kc + 2, (kc & 1) ? XS1 : XS0); }
            CP_COMMIT();

#pragma unroll
            for (int np = 0; np < 4; np++) {
#pragma unroll
                for (int kf = 0; kf < 4; kf++) {
                    int krow = kc * 64 + kf * 16 + (mat & 1) * 8 + r;
                    uint32_t bc = (uint32_t)(np * 32 + (mat >> 1) * 16);
                    uint32_t off = (uint32_t)(krow * 128)
                                 + (bc ^ (uint32_t)((krow & 7) << 4));
                    uint32_t b0, b1, b2, b3;
                    LDSM_X4T(b0, b1, b2, b3, sb + OFF_WQ + off);
#pragma unroll
                    for (int mt = 0; mt < 2; mt++) {
                        MMA_F16(qacc[mt][2 * np],     ax[mt][kf][0], ax[mt][kf][1],
                                ax[mt][kf][2], ax[mt][kf][3], b0, b1);
                        MMA_F16(qacc[mt][2 * np + 1], ax[mt][kf][0], ax[mt][kf][1],
                                ax[mt][kf][2], ax[mt][kf][3], b2, b3);
                    }
                }
            }
        }

        // C-frag -> A-frag pack with scale (0.125 * log2e folded in)
        const float sc = 0.125f * LOG2E;
#pragma unroll
        for (int mt = 0; mt < 2; mt++)
#pragma unroll
            for (int kf = 0; kf < 4; kf++) {
                qh[mt][kf][0] = pack_h2(qacc[mt][2*kf][0] * sc,   qacc[mt][2*kf][1] * sc);
                qh[mt][kf][1] = pack_h2(qacc[mt][2*kf][2] * sc,   qacc[mt][2*kf][3] * sc);
                qh[mt][kf][2] = pack_h2(qacc[mt][2*kf+1][0] * sc, qacc[mt][2*kf+1][1] * sc);
                qh[mt][kf][3] = pack_h2(qacc[mt][2*kf+1][2] * sc, qacc[mt][2*kf+1][3] * sc);
            }
        __syncthreads();   // prologue smem fully consumed (ring reuses it)
    }
    // ================= end prologue =================

    float oacc[2][8][4];
#pragma unroll
    for (int mt = 0; mt < 2; mt++)
#pragma unroll
        for (int n = 0; n < 8; n++)
#pragma unroll
            for (int j = 0; j < 4; j++) oacc[mt][n][j] = 0.f;
    float ll[2][2] = {{0.f, 0.f}, {0.f, 0.f}};

    const uint4* k4 = (const uint4*)(K + (size_t)(bb * NDIM) * 64);
    const uint4* v4 = (const uint4*)(V + (size_t)(bb * NDIM) * 64);

    issue_tile(sb, 0,     0, t, k4, v4); CP_COMMIT();
    issue_tile(sb, 32768, 1, t, k4, v4); CP_COMMIT();
    issue_tile(sb, 65536, 2, t, k4, v4); CP_COMMIT();

    for (int nt = 0; nt < NDIM / 128; ++nt) {
        CP_WAIT2();
        __syncthreads();
        const uint32_t buf = (uint32_t)(nt % 3) * 32768u;

        uint32_t pa[2][4];
        uint32_t vb[4][4];

#pragma unroll
        for (int tp = 0; tp < 5; tp++) {
            if (tp > 0) {
                const int kgp = kw * 4 + tp - 1;
                const uint32_t rowa = (uint32_t)((kgp * 16 + (mat & 1) * 8 + r) * 128);
#pragma unroll
                for (int hp = 0; hp < 4; hp++) {
                    uint32_t av = sb + buf + 16384 + rowa
                                + (uint32_t)((hp * 32 + (mat >> 1) * 16) ^ (r << 4));
                    LDSM_X4T(vb[hp][0], vb[hp][1], vb[hp][2], vb[hp][3], av);
                }
            }

            uint32_t kb[4][4];
            if (tp < 4) {
                const int kg = kw * 4 + tp;
                const uint32_t rowb = (uint32_t)((kg * 16 + (mat >> 1) * 8 + r) * 128);
#pragma unroll
                for (int kf = 0; kf < 4; kf++) {
                    uint32_t a = sb + buf + rowb
                               + (uint32_t)((kf * 32 + (mat & 1) * 16) ^ (r << 4));
                    LDSM_X4(kb[kf][0], kb[kf][1], kb[kf][2], kb[kf][3], a);
                }
            }

            if (tp > 0) {
#pragma unroll
                for (int hp = 0; hp < 4; hp++)
#pragma unroll
                    for (int mt = 0; mt < 2; mt++) {
                        MMA_F16(oacc[mt][2 * hp],     pa[mt][0], pa[mt][1],
                                pa[mt][2], pa[mt][3], vb[hp][0], vb[hp][1]);
                        MMA_F16(oacc[mt][2 * hp + 1], pa[mt][0], pa[mt][1],
                                pa[mt][2], pa[mt][3], vb[hp][2], vb[hp][3]);
                    }
            }

            if (tp < 4) {
                float s[2][2][4];
#pragma unroll
                for (int mt = 0; mt < 2; mt++) {
#pragma unroll
                    for (int nb = 0; nb < 2; nb++)
#pragma unroll
                        for (int j = 0; j < 4; j++) s[mt][nb][j] = 0.f;
#pragma unroll
                    for (int kf = 0; kf < 4; kf++) {
                        MMA_F16(s[mt][0], qh[mt][kf][0], qh[mt][kf][1],
                                qh[mt][kf][2], qh[mt][kf][3], kb[kf][0], kb[kf][1]);
                        MMA_F16(s[mt][1], qh[mt][kf][0], qh[mt][kf][1],
                                qh[mt][kf][2], qh[mt][kf][3], kb[kf][2], kb[kf][3]);
                    }
                }
#pragma unroll
                for (int mt = 0; mt < 2; mt++) {
                    float e00 = ex2f(s[mt][0][0]), e01 = ex2f(s[mt][0][1]);
                    float e02 = ex2f(s[mt][0][2]), e03 = ex2f(s[mt][0][3]);
                    float e10 = ex2f(s[mt][1][0]), e11 = ex2f(s[mt][1][1]);
                    float e12 = ex2f(s[mt][1][2]), e13 = ex2f(s[mt][1][3]);
                    ll[mt][0] += e00 + e01 + e10 + e11;
                    ll[mt][1] += e02 + e03 + e12 + e13;
                    pa[mt][0] = pack_h2(e00, e01); pa[mt][1] = pack_h2(e02, e03);
                    pa[mt][2] = pack_h2(e10, e11); pa[mt][3] = pack_h2(e12, e13);
                }
            }
        }

        __syncthreads();
        if (nt + 3 < NDIM / 128)
            issue_tile(sb, buf, nt + 3, t, k4, v4);
        CP_COMMIT();
    }

#pragma unroll
    for (int mt = 0; mt < 2; mt++)
#pragma unroll
        for (int h = 0; h < 2; h++) {
            ll[mt][h] += __shfl_xor_sync(0xffffffffu, ll[mt][h], 1);
            ll[mt][h] += __shfl_xor_sync(0xffffffffu, ll[mt][h], 2);
        }

    __syncthreads();
    float* Osm = (float*)smem;             // [64 rows][64 cols]
    float* lsm = (float*)(smem + 16384);   // [64 rows]

    if (kw == 1) {
#pragma unroll
        for (int mt = 0; mt < 2; mt++) {
            int rr = mw * 32 + mt * 16 + g;
            float* d0 = Osm + rr * 64;
            float* d1 = d0 + 8 * 64;
#pragma unroll
            for (int n = 0; n < 8; n++) {
                int col = n * 8 + q4 * 2;
                *(float2*)(d0 + col) = make_float2(oacc[mt][n][0], oacc[mt][n][1]);
                *(float2*)(d1 + col) = make_float2(oacc[mt][n][2], oacc[mt][n][3]);
            }
            if (q4 == 0) {
                lsm[rr]     = ll[mt][0];
                lsm[rr + 8] = ll[mt][1];
            }
        }
    }
    __syncthreads();

    if (kw == 0) {
#pragma unroll
        for (int mt = 0; mt < 2; mt++) {
            int rr = mw * 32 + mt * 16 + g;
            const float* s0 = Osm + rr * 64;
            const float* s1 = s0 + 8 * 64;
            const float i0 = 1.f / (ll[mt][0] + lsm[rr]);
            const float i1 = 1.f / (ll[mt][1] + lsm[rr + 8]);
            float* Og0 = O + ((size_t)(bb * MDIM + m0 + rr)) * 64;
            float* Og1 = Og0 + 8 * 64;
#pragma unroll
            for (int n = 0; n < 8; n++) {
                int col = n * 8 + q4 * 2;
                float2 a0 = *(const float2*)(s0 + col);
                float2 a1 = *(const float2*)(s1 + col);
                *(float2*)(Og0 + col) = make_float2((oacc[mt][n][0] + a0.x) * i0,
                                                    (oacc[mt][n][1] + a0.y) * i0);
                *(float2*)(Og1 + col) = make_float2((oacc[mt][n][2] + a1.x) * i1,
                                                    (oacc[mt][n][3] + a1.y) * i1);
            }
        }
    }
}

// ---------------------------------------------------------------------------
// Launch
// ---------------------------------------------------------------------------
extern "C" void kernel_launch(void* const* d_in, const int* in_sizes, int n_in,
                              void* d_out, int out_size)
{
    const float* x    = (const float*)d_in[0];
    const float* cond = (const float*)d_in[1];
    const float* Wq   = (const float*)d_in[2];
    const float* Wkv  = (const float*)d_in[3];
    float* out = (float*)d_out;

    __half *k, *v;
    cudaGetSymbolAddress((void**)&k, g_k);
    cudaGetSymbolAddress((void**)&v, g_v);

    cudaFuncSetAttribute(kv_proj,
                         cudaFuncAttributeMaxDynamicSharedMemorySize, 57344);
    cudaFuncSetAttribute(attn_kernel,
                         cudaFuncAttributeMaxDynamicSharedMemorySize, 98304);

    kv_proj<<<BATCH * NDIM / 64, 128, 57344>>>(cond, Wkv, k, v);

    dim3 grid(MDIM / 64, BATCH);
    attn_kernel<<<grid, 128, 98304>>>(x, Wq, k, v, out);
}

// round 16
// speedup vs baseline: 1.1222x; 1.0310x over previous
#include <cuda_runtime.h>
#include <cuda_bf16.h>
#include <cuda_fp16.h>
#include <cstdint>
#include <cstddef>

#define BATCH 4
#define MDIM  4096
#define NDIM  4096
#define DQK   256

static constexpr float LOG2E = 1.4426950408889634f;

// ---------------------------------------------------------------------------
// helpers
// ---------------------------------------------------------------------------
__device__ __forceinline__ uint32_t smem_u32(const void* p) {
    uint32_t a;
    asm("{ .reg .u64 t; cvta.to.shared.u64 t, %1; cvt.u32.u64 %0, t; }"
        : "=r"(a) : "l"(p));
    return a;
}

__device__ __forceinline__ float ex2f(float x) {
    float r; asm("ex2.approx.ftz.f32 %0, %1;" : "=f"(r) : "f"(x)); return r;
}

__device__ __forceinline__ uint32_t pack_h2(float a, float b) {
    __half2 h = __floats2half2_rn(a, b);
    return *reinterpret_cast<uint32_t*>(&h);
}

#define LDSM_X4(r0, r1, r2, r3, a) \
    asm volatile("ldmatrix.sync.aligned.m8n8.x4.shared.b16 {%0,%1,%2,%3}, [%4];" \
                 : "=r"(r0), "=r"(r1), "=r"(r2), "=r"(r3) : "r"(a))

#define LDSM_X4T(r0, r1, r2, r3, a) \
    asm volatile("ldmatrix.sync.aligned.m8n8.x4.trans.shared.b16 {%0,%1,%2,%3}, [%4];" \
                 : "=r"(r0), "=r"(r1), "=r"(r2), "=r"(r3) : "r"(a))

#define MMA_F16(d, a0, a1, a2, a3, b0, b1)                                     \
    asm volatile("mma.sync.aligned.m16n8k16.row.col.f32.f16.f16.f32 "          \
                 "{%0,%1,%2,%3}, {%4,%5,%6,%7}, {%8,%9}, {%0,%1,%2,%3};"       \
                 : "+f"((d)[0]), "+f"((d)[1]), "+f"((d)[2]), "+f"((d)[3])      \
                 : "r"(a0), "r"(a1), "r"(a2), "r"(a3), "r"(b0), "r"(b1))

#define CP_ASYNC16(dst, src) \
    asm volatile("cp.async.cg.shared.global [%0], [%1], 16;" \
                 :: "r"(dst), "l"(src) : "memory")
#define CP_COMMIT() asm volatile("cp.async.commit_group;" ::: "memory")
#define CP_WAIT0()  asm volatile("cp.async.wait_group 0;" ::: "memory")
#define CP_WAIT1()  asm volatile("cp.async.wait_group 1;" ::: "memory")
#define CP_WAIT2()  asm volatile("cp.async.wait_group 2;" ::: "memory")

// ---------------------------------------------------------------------------
// scratch: fp16 K, V — row-major [b*4096+n][64]
// ---------------------------------------------------------------------------
__device__ __half g_k[(size_t)BATCH * NDIM * 64];
__device__ __half g_v[(size_t)BATCH * NDIM * 64];

// ---------------------------------------------------------------------------
// KV projection (R12 version verbatim — measured 8.3us):
// 64 rows/CTA, 128 threads (4 warps x 16 rows), grid 256.
// cp.async double-buffered A staging, per-chunk W16 staging.
// smem: A16 @0 (8KB), W16 @8K (16KB), A32 stages @24K (2 x 16KB) = 56KB.
// ---------------------------------------------------------------------------
__global__ void __launch_bounds__(128, 2) kv_proj(
    const float* __restrict__ A, const float* __restrict__ W,
    __half* __restrict__ ko, __half* __restrict__ vo)
{
    extern __shared__ char sm[];
    const uint32_t sb = smem_u32(sm);
    constexpr uint32_t OFF_W   = 8192;
    constexpr uint32_t OFF_A32 = 24576;

    const int t = threadIdx.x, w = t >> 5, lane = t & 31;
    const int mat = lane >> 3, r = lane & 7;
    const int g = lane >> 2, q4 = lane & 3;
    const int r0 = blockIdx.x * 64;

    float acc[16][4];
#pragma unroll
    for (int j = 0; j < 16; j++)
#pragma unroll
        for (int i = 0; i < 4; i++) acc[j][i] = 0.f;

    auto issueA = [&](int kc, uint32_t stage) {
        const float* src = A + (size_t)r0 * DQK + kc * 64;
#pragma unroll
        for (int i = t; i < 1024; i += 128) {
            int row = i >> 4, c4 = i & 15;
            CP_ASYNC16(sb + OFF_A32 + stage * 16384u + (uint32_t)i * 16u,
                       src + (size_t)row * DQK + c4 * 4);
        }
    };

    issueA(0, 0); CP_COMMIT();
    issueA(1, 1); CP_COMMIT();

    for (int kc = 0; kc < 4; kc++) {
        if (kc) __syncthreads();

        // W chunk [64 x 128] fp32 -> fp16
#pragma unroll
        for (int i = t; i < 2048; i += 128) {
            int kr = i >> 5, c4 = i & 31;
            float4 v = *(const float4*)(W + (size_t)(kc * 64 + kr) * 128 + c4 * 4);
            uint32_t h0 = pack_h2(v.x, v.y);
            uint32_t h1 = pack_h2(v.z, v.w);
            uint32_t bc = (uint32_t)(c4 * 8);
            uint32_t off = (uint32_t)(kr * 256) + (bc & ~127u)
                         + ((bc & 127u) ^ (uint32_t)((kr & 7) << 4));
            *(uint2*)(sm + OFF_W + off) = make_uint2(h0, h1);
        }

        if (kc == 3) { CP_WAIT0(); } else { CP_WAIT1(); }
        const uint32_t stg = OFF_A32 + (uint32_t)(kc & 1) * 16384u;
#pragma unroll
        for (int i = t; i < 1024; i += 128) {
            int row = i >> 4, c4 = i & 15;
            float4 v = *(const float4*)(sm + stg + (uint32_t)i * 16u);
            uint32_t h0 = pack_h2(v.x, v.y);
            uint32_t h1 = pack_h2(v.z, v.w);
            uint32_t off = (uint32_t)(row * 128) + (uint32_t)((c4 * 8) ^ ((row & 7) << 4));
            *(uint2*)(sm + off) = make_uint2(h0, h1);
        }
        __syncthreads();

        if (kc + 2 < 4) { issueA(kc + 2, (uint32_t)(kc & 1)); }
        CP_COMMIT();

        uint32_t ah[4][4];
#pragma unroll
        for (int kf = 0; kf < 4; kf++) {
            uint32_t off = (uint32_t)((w * 16 + (mat & 1) * 8 + r) * 128)
                         + (uint32_t)((kf * 32 + (mat >> 1) * 16) ^ (r << 4));
            LDSM_X4(ah[kf][0], ah[kf][1], ah[kf][2], ah[kf][3], sb + off);
        }
#pragma unroll
        for (int np = 0; np < 8; np++) {
#pragma unroll
            for (int kf = 0; kf < 4; kf++) {
                int krow = kf * 16 + (mat & 1) * 8 + r;
                uint32_t bc = (uint32_t)(np * 32 + (mat >> 1) * 16);
                uint32_t off = (uint32_t)(krow * 256) + (bc & ~127u)
                             + ((bc & 127u) ^ (uint32_t)((krow & 7) << 4));
                uint32_t b0, b1, b2, b3;
                LDSM_X4T(b0, b1, b2, b3, sb + OFF_W + off);
                MMA_F16(acc[2 * np],     ah[kf][0], ah[kf][1], ah[kf][2], ah[kf][3], b0, b1);
                MMA_F16(acc[2 * np + 1], ah[kf][0], ah[kf][1], ah[kf][2], ah[kf][3], b2, b3);
            }
        }
    }

    const int row = r0 + w * 16 + g;
#pragma unroll
    for (int j = 0; j < 16; j++) {
        uint32_t p01 = pack_h2(acc[j][0], acc[j][1]);
        uint32_t p23 = pack_h2(acc[j][2], acc[j][3]);
        int col = j * 8 + q4 * 2;
        __half* dst = (col < 64) ? ko : vo;
        int cc = (col < 64) ? col : col - 64;
        *(uint32_t*)(dst + (size_t)row * 64 + cc)       = p01;
        *(uint32_t*)(dst + (size_t)(row + 8) * 64 + cc) = p23;
    }
}

// ---------------------------------------------------------------------------
// Attention (fp16) with fused Q projection (R12 mechanism, overlapped):
//  - ring tile 0 prefetched BEFORE the prologue (stage-0 smem disjoint)
//  - prologue buffers relocated to 32K..82K: x16 dbl-buf @32K/@40K, Wq16 @48K
//  - x16 staging double-buffered: next chunk's LDG burst issues before the
//    current chunk's MMAs (latency hidden), 1 sync per chunk
// Mainloop identical to R8/R10/R11 best.
// ---------------------------------------------------------------------------
__device__ __forceinline__ void issue_tile(
    uint32_t sb, uint32_t buf, int nt, int t,
    const uint4* k4, const uint4* v4)
{
    const uint4* k = k4 + nt * 1024;
    const uint4* v = v4 + nt * 1024;
#pragma unroll
    for (int i = t; i < 1024; i += 128) {
        int row = i >> 3, c = i & 7;
        uint32_t off = buf + (uint32_t)(row * 128)
                     + (uint32_t)((c * 16) ^ ((row & 7) << 4));
        CP_ASYNC16(sb + off,         k + i);
        CP_ASYNC16(sb + off + 16384, v + i);
    }
}

__global__ void __launch_bounds__(128, 2) attn_kernel(
    const float* __restrict__ X, const float* __restrict__ Wq,
    const __half* __restrict__ K, const __half* __restrict__ V,
    float* __restrict__ O)
{
    extern __shared__ char smem[];
    const uint32_t sb = smem_u32(smem);

    const int t    = threadIdx.x;
    const int w    = t >> 5, lane = t & 31;
    const int mw   = w >> 1, kw = w & 1;
    const int g    = lane >> 2, q4 = lane & 3;
    const int mat  = lane >> 3, r = lane & 7;
    const int bb   = blockIdx.y;
    const int m0   = blockIdx.x * 64;

    const uint4* k4 = (const uint4*)(K + (size_t)(bb * NDIM) * 64);
    const uint4* v4 = (const uint4*)(V + (size_t)(bb * NDIM) * 64);

    // ring tile 0 in flight during the whole prologue
    issue_tile(sb, 0, 0, t, k4, v4); CP_COMMIT();

    // ================= Q-projection prologue =================
    uint32_t qh[2][4][4];
    {
        constexpr uint32_t XA     = 32768;   // x16 buffer A (8 KB)
        constexpr uint32_t XB     = 40960;   // x16 buffer B (8 KB)
        constexpr uint32_t OFF_WQ = 49152;   // Wq16 (32 KB, ends 81920)

        const float* Xb = X + (size_t)(bb * MDIM + m0) * DQK;

        auto stageX = [&](int kc, uint32_t dst) {
#pragma unroll
            for (int i = t; i < 1024; i += 128) {
                int row = i >> 4, c4 = i & 15;
                float4 v = *(const float4*)(Xb + (size_t)row * DQK + kc * 64 + c4 * 4);
                uint32_t h0 = pack_h2(v.x, v.y);
                uint32_t h1 = pack_h2(v.z, v.w);
                uint32_t off = (uint32_t)(row * 128)
                             + (uint32_t)((c4 * 8) ^ ((row & 7) << 4));
                *(uint2*)(smem + dst + off) = make_uint2(h0, h1);
            }
        };

        // stage Wq16 once (256 rows x 128 B, swizzled) + x chunk 0
#pragma unroll 4
        for (int i = t; i < 4096; i += 128) {
            int kr = i >> 4, c4 = i & 15;
            float4 v = *(const float4*)(Wq + (size_t)kr * 64 + c4 * 4);
            uint32_t h0 = pack_h2(v.x, v.y);
            uint32_t h1 = pack_h2(v.z, v.w);
            uint32_t bc = (uint32_t)(c4 * 8);
            uint32_t off = (uint32_t)(kr * 128) + (bc ^ (uint32_t)((kr & 7) << 4));
            *(uint2*)(smem + OFF_WQ + off) = make_uint2(h0, h1);
        }
        stageX(0, XA);
        __syncthreads();

        float qacc[2][8][4];
#pragma unroll
        for (int mt = 0; mt < 2; mt++)
#pragma unroll
            for (int j = 0; j < 8; j++)
#pragma unroll
                for (int i = 0; i < 4; i++) qacc[mt][j][i] = 0.f;

#pragma unroll
        for (int kc = 0; kc < 4; kc++) {
            // issue next chunk's LDG burst first — hides under MMAs below
            if (kc < 3) stageX(kc + 1, (kc & 1) ? XA : XB);

            const uint32_t xs = (kc & 1) ? XB : XA;
            uint32_t ax[2][4][4];
#pragma unroll
            for (int mt = 0; mt < 2; mt++)
#pragma unroll
                for (int kf = 0; kf < 4; kf++) {
                    uint32_t off = (uint32_t)((mw * 32 + mt * 16 + (mat & 1) * 8 + r) * 128)
                                 + (uint32_t)((kf * 32 + (mat >> 1) * 16) ^ (r << 4));
                    LDSM_X4(ax[mt][kf][0], ax[mt][kf][1], ax[mt][kf][2], ax[mt][kf][3],
                            sb + xs + off);
                }
#pragma unroll
            for (int np = 0; np < 4; np++) {
#pragma unroll
                for (int kf = 0; kf < 4; kf++) {
                    int krow = kc * 64 + kf * 16 + (mat & 1) * 8 + r;
                    uint32_t bc = (uint32_t)(np * 32 + (mat >> 1) * 16);
                    uint32_t off = (uint32_t)(krow * 128)
                                 + (bc ^ (uint32_t)((krow & 7) << 4));
                    uint32_t b0, b1, b2, b3;
                    LDSM_X4T(b0, b1, b2, b3, sb + OFF_WQ + off);
#pragma unroll
                    for (int mt = 0; mt < 2; mt++) {
                        MMA_F16(qacc[mt][2 * np],     ax[mt][kf][0], ax[mt][kf][1],
                                ax[mt][kf][2], ax[mt][kf][3], b0, b1);
                        MMA_F16(qacc[mt][2 * np + 1], ax[mt][kf][0], ax[mt][kf][1],
                                ax[mt][kf][2], ax[mt][kf][3], b2, b3);
                    }
                }
            }
            if (kc < 3) __syncthreads();
        }

        // C-frag -> A-frag pack with scale (0.125 * log2e folded in)
        const float sc = 0.125f * LOG2E;
#pragma unroll
        for (int mt = 0; mt < 2; mt++)
#pragma unroll
            for (int kf = 0; kf < 4; kf++) {
                qh[mt][kf][0] = pack_h2(qacc[mt][2*kf][0] * sc,   qacc[mt][2*kf][1] * sc);
                qh[mt][kf][1] = pack_h2(qacc[mt][2*kf][2] * sc,   qacc[mt][2*kf][3] * sc);
                qh[mt][kf][2] = pack_h2(qacc[mt][2*kf+1][0] * sc, qacc[mt][2*kf+1][1] * sc);
                qh[mt][kf][3] = pack_h2(qacc[mt][2*kf+1][2] * sc, qacc[mt][2*kf+1][3] * sc);
            }
        __syncthreads();   // prologue smem (stages 1,2 region) fully consumed
    }
    issue_tile(sb, 32768, 1, t, k4, v4); CP_COMMIT();
    issue_tile(sb, 65536, 2, t, k4, v4); CP_COMMIT();
    // ================= end prologue =================

    float oacc[2][8][4];
#pragma unroll
    for (int mt = 0; mt < 2; mt++)
#pragma unroll
        for (int n = 0; n < 8; n++)
#pragma unroll
            for (int j = 0; j < 4; j++) oacc[mt][n][j] = 0.f;
    float ll[2][2] = {{0.f, 0.f}, {0.f, 0.f}};

    for (int nt = 0; nt < NDIM / 128; ++nt) {
        CP_WAIT2();
        __syncthreads();
        const uint32_t buf = (uint32_t)(nt % 3) * 32768u;

        uint32_t pa[2][4];
        uint32_t vb[4][4];

#pragma unroll
        for (int tp = 0; tp < 5; tp++) {
            if (tp > 0) {
                const int kgp = kw * 4 + tp - 1;
                const uint32_t rowa = (uint32_t)((kgp * 16 + (mat & 1) * 8 + r) * 128);
#pragma unroll
                for (int hp = 0; hp < 4; hp++) {
                    uint32_t av = sb + buf + 16384 + rowa
                                + (uint32_t)((hp * 32 + (mat >> 1) * 16) ^ (r << 4));
                    LDSM_X4T(vb[hp][0], vb[hp][1], vb[hp][2], vb[hp][3], av);
                }
            }

            uint32_t kb[4][4];
            if (tp < 4) {
                const int kg = kw * 4 + tp;
                const uint32_t rowb = (uint32_t)((kg * 16 + (mat >> 1) * 8 + r) * 128);
#pragma unroll
                for (int kf = 0; kf < 4; kf++) {
                    uint32_t a = sb + buf + rowb
                               + (uint32_t)((kf * 32 + (mat & 1) * 16) ^ (r << 4));
                    LDSM_X4(kb[kf][0], kb[kf][1], kb[kf][2], kb[kf][3], a);
                }
            }

            if (tp > 0) {
#pragma unroll
                for (int hp = 0; hp < 4; hp++)
#pragma unroll
                    for (int mt = 0; mt < 2; mt++) {
                        MMA_F16(oacc[mt][2 * hp],     pa[mt][0], pa[mt][1],
                                pa[mt][2], pa[mt][3], vb[hp][0], vb[hp][1]);
                        MMA_F16(oacc[mt][2 * hp + 1], pa[mt][0], pa[mt][1],
                                pa[mt][2], pa[mt][3], vb[hp][2], vb[hp][3]);
                    }
            }

            if (tp < 4) {
                float s[2][2][4];
#pragma unroll
                for (int mt = 0; mt < 2; mt++) {
#pragma unroll
                    for (int nb = 0; nb < 2; nb++)
#pragma unroll
                        for (int j = 0; j < 4; j++) s[mt][nb][j] = 0.f;
#pragma unroll
                    for (int kf = 0; kf < 4; kf++) {
                        MMA_F16(s[mt][0], qh[mt][kf][0], qh[mt][kf][1],
                                qh[mt][kf][2], qh[mt][kf][3], kb[kf][0], kb[kf][1]);
                        MMA_F16(s[mt][1], qh[mt][kf][0], qh[mt][kf][1],
                                qh[mt][kf][2], qh[mt][kf][3], kb[kf][2], kb[kf][3]);
                    }
                }
#pragma unroll
                for (int mt = 0; mt < 2; mt++) {
                    float e00 = ex2f(s[mt][0][0]), e01 = ex2f(s[mt][0][1]);
                    float e02 = ex2f(s[mt][0][2]), e03 = ex2f(s[mt][0][3]);
                    float e10 = ex2f(s[mt][1][0]), e11 = ex2f(s[mt][1][1]);
                    float e12 = ex2f(s[mt][1][2]), e13 = ex2f(s[mt][1][3]);
                    ll[mt][0] += e00 + e01 + e10 + e11;
                    ll[mt][1] += e02 + e03 + e12 + e13;
                    pa[mt][0] = pack_h2(e00, e01); pa[mt][1] = pack_h2(e02, e03);
                    pa[mt][2] = pack_h2(e10, e11); pa[mt][3] = pack_h2(e12, e13);
                }
            }
        }

        __syncthreads();
        if (nt + 3 < NDIM / 128)
            issue_tile(sb, buf, nt + 3, t, k4, v4);
        CP_COMMIT();
    }

#pragma unroll
    for (int mt = 0; mt < 2; mt++)
#pragma unroll
        for (int h = 0; h < 2; h++) {
            ll[mt][h] += __shfl_xor_sync(0xffffffffu, ll[mt][h], 1);
            ll[mt][h] += __shfl_xor_sync(0xffffffffu, ll[mt][h], 2);
        }

    __syncthreads();
    float* Osm = (float*)smem;             // [64 rows][64 cols]
    float* lsm = (float*)(smem + 16384);   // [64 rows]

    if (kw == 1) {
#pragma unroll
        for (int mt = 0; mt < 2; mt++) {
            int rr = mw * 32 + mt * 16 + g;
            float* d0 = Osm + rr * 64;
            float* d1 = d0 + 8 * 64;
#pragma unroll
            for (int n = 0; n < 8; n++) {
                int col = n * 8 + q4 * 2;
                *(float2*)(d0 + col) = make_float2(oacc[mt][n][0], oacc[mt][n][1]);
                *(float2*)(d1 + col) = make_float2(oacc[mt][n][2], oacc[mt][n][3]);
            }
            if (q4 == 0) {
                lsm[rr]     = ll[mt][0];
                lsm[rr + 8] = ll[mt][1];
            }
        }
    }
    __syncthreads();

    if (kw == 0) {
#pragma unroll
        for (int mt = 0; mt < 2; mt++) {
            int rr = mw * 32 + mt * 16 + g;
            const float* s0 = Osm + rr * 64;
            const float* s1 = s0 + 8 * 64;
            const float i0 = 1.f / (ll[mt][0] + lsm[rr]);
            const float i1 = 1.f / (ll[mt][1] + lsm[rr + 8]);
            float* Og0 = O + ((size_t)(bb * MDIM + m0 + rr)) * 64;
            float* Og1 = Og0 + 8 * 64;
#pragma unroll
            for (int n = 0; n < 8; n++) {
                int col = n * 8 + q4 * 2;
                float2 a0 = *(const float2*)(s0 + col);
                float2 a1 = *(const float2*)(s1 + col);
                *(float2*)(Og0 + col) = make_float2((oacc[mt][n][0] + a0.x) * i0,
                                                    (oacc[mt][n][1] + a0.y) * i0);
                *(float2*)(Og1 + col) = make_float2((oacc[mt][n][2] + a1.x) * i1,
                                                    (oacc[mt][n][3] + a1.y) * i1);
            }
        }
    }
}

// ---------------------------------------------------------------------------
// Launch
// ---------------------------------------------------------------------------
extern "C" void kernel_launch(void* const* d_in, const int* in_sizes, int n_in,
                              void* d_out, int out_size)
{
    const float* x    = (const float*)d_in[0];
    const float* cond = (const float*)d_in[1];
    const float* Wq   = (const float*)d_in[2];
    const float* Wkv  = (const float*)d_in[3];
    float* out = (float*)d_out;

    __half *k, *v;
    cudaGetSymbolAddress((void**)&k, g_k);
    cudaGetSymbolAddress((void**)&v, g_v);

    cudaFuncSetAttribute(kv_proj,
                         cudaFuncAttributeMaxDynamicSharedMemorySize, 57344);
    cudaFuncSetAttribute(attn_kernel,
                         cudaFuncAttributeMaxDynamicSharedMemorySize, 98304);

    kv_proj<<<BATCH * NDIM / 64, 128, 57344>>>(cond, Wkv, k, v);

    dim3 grid(MDIM / 64, BATCH);
    attn_kernel<<<grid, 128, 98304>>>(x, Wq, k, v, out);
}

// round 17
// speedup vs baseline: 1.1227x; 1.0005x over previous
#include <cuda_runtime.h>
#include <cuda_bf16.h>
#include <cuda_fp16.h>
#include <cstdint>
#include <cstddef>

#define BATCH 4
#define MDIM  4096
#define NDIM  4096
#define DQK   256

static constexpr float LOG2E = 1.4426950408889634f;

// ---------------------------------------------------------------------------
// helpers
// ---------------------------------------------------------------------------
__device__ __forceinline__ uint32_t smem_u32(const void* p) {
    uint32_t a;
    asm("{ .reg .u64 t; cvta.to.shared.u64 t, %1; cvt.u32.u64 %0, t; }"
        : "=r"(a) : "l"(p));
    return a;
}

__device__ __forceinline__ float ex2f(float x) {
    float r; asm("ex2.approx.ftz.f32 %0, %1;" : "=f"(r) : "f"(x)); return r;
}

__device__ __forceinline__ uint32_t pack_h2(float a, float b) {
    __half2 h = __floats2half2_rn(a, b);
    return *reinterpret_cast<uint32_t*>(&h);
}

#define LDSM_X4(r0, r1, r2, r3, a) \
    asm volatile("ldmatrix.sync.aligned.m8n8.x4.shared.b16 {%0,%1,%2,%3}, [%4];" \
                 : "=r"(r0), "=r"(r1), "=r"(r2), "=r"(r3) : "r"(a))

#define LDSM_X4T(r0, r1, r2, r3, a) \
    asm volatile("ldmatrix.sync.aligned.m8n8.x4.trans.shared.b16 {%0,%1,%2,%3}, [%4];" \
                 : "=r"(r0), "=r"(r1), "=r"(r2), "=r"(r3) : "r"(a))

#define MMA_F16(d, a0, a1, a2, a3, b0, b1)                                     \
    asm volatile("mma.sync.aligned.m16n8k16.row.col.f32.f16.f16.f32 "          \
                 "{%0,%1,%2,%3}, {%4,%5,%6,%7}, {%8,%9}, {%0,%1,%2,%3};"       \
                 : "+f"((d)[0]), "+f"((d)[1]), "+f"((d)[2]), "+f"((d)[3])      \
                 : "r"(a0), "r"(a1), "r"(a2), "r"(a3), "r"(b0), "r"(b1))

#define CP_ASYNC16(dst, src) \
    asm volatile("cp.async.cg.shared.global [%0], [%1], 16;" \
                 :: "r"(dst), "l"(src) : "memory")
#define CP_COMMIT() asm volatile("cp.async.commit_group;" ::: "memory")
#define CP_WAIT0()  asm volatile("cp.async.wait_group 0;" ::: "memory")
#define CP_WAIT1()  asm volatile("cp.async.wait_group 1;" ::: "memory")
#define CP_WAIT2()  asm volatile("cp.async.wait_group 2;" ::: "memory")

// ---------------------------------------------------------------------------
// scratch: fp16 K, V — row-major [b*4096+n][64]
// ---------------------------------------------------------------------------
__device__ __half g_k[(size_t)BATCH * NDIM * 64];
__device__ __half g_v[(size_t)BATCH * NDIM * 64];

// ---------------------------------------------------------------------------
// KV projection (R12 structure; MMA nest reordered kf-outer for 16-deep
// independent chains): 64 rows/CTA, 128 threads, grid 256.
// ---------------------------------------------------------------------------
__global__ void __launch_bounds__(128, 2) kv_proj(
    const float* __restrict__ A, const float* __restrict__ W,
    __half* __restrict__ ko, __half* __restrict__ vo)
{
    extern __shared__ char sm[];
    const uint32_t sb = smem_u32(sm);
    constexpr uint32_t OFF_W   = 8192;
    constexpr uint32_t OFF_A32 = 24576;

    const int t = threadIdx.x, w = t >> 5, lane = t & 31;
    const int mat = lane >> 3, r = lane & 7;
    const int g = lane >> 2, q4 = lane & 3;
    const int r0 = blockIdx.x * 64;

    float acc[16][4];
#pragma unroll
    for (int j = 0; j < 16; j++)
#pragma unroll
        for (int i = 0; i < 4; i++) acc[j][i] = 0.f;

    auto issueA = [&](int kc, uint32_t stage) {
        const float* src = A + (size_t)r0 * DQK + kc * 64;
#pragma unroll
        for (int i = t; i < 1024; i += 128) {
            int row = i >> 4, c4 = i & 15;
            CP_ASYNC16(sb + OFF_A32 + stage * 16384u + (uint32_t)i * 16u,
                       src + (size_t)row * DQK + c4 * 4);
        }
    };

    issueA(0, 0); CP_COMMIT();
    issueA(1, 1); CP_COMMIT();

    for (int kc = 0; kc < 4; kc++) {
        if (kc) __syncthreads();

#pragma unroll
        for (int i = t; i < 2048; i += 128) {
            int kr = i >> 5, c4 = i & 31;
            float4 v = *(const float4*)(W + (size_t)(kc * 64 + kr) * 128 + c4 * 4);
            uint32_t h0 = pack_h2(v.x, v.y);
            uint32_t h1 = pack_h2(v.z, v.w);
            uint32_t bc = (uint32_t)(c4 * 8);
            uint32_t off = (uint32_t)(kr * 256) + (bc & ~127u)
                         + ((bc & 127u) ^ (uint32_t)((kr & 7) << 4));
            *(uint2*)(sm + OFF_W + off) = make_uint2(h0, h1);
        }

        if (kc == 3) { CP_WAIT0(); } else { CP_WAIT1(); }
        const uint32_t stg = OFF_A32 + (uint32_t)(kc & 1) * 16384u;
#pragma unroll
        for (int i = t; i < 1024; i += 128) {
            int row = i >> 4, c4 = i & 15;
            float4 v = *(const float4*)(sm + stg + (uint32_t)i * 16u);
            uint32_t h0 = pack_h2(v.x, v.y);
            uint32_t h1 = pack_h2(v.z, v.w);
            uint32_t off = (uint32_t)(row * 128) + (uint32_t)((c4 * 8) ^ ((row & 7) << 4));
            *(uint2*)(sm + off) = make_uint2(h0, h1);
        }
        __syncthreads();

        if (kc + 2 < 4) { issueA(kc + 2, (uint32_t)(kc & 1)); }
        CP_COMMIT();

        uint32_t ah[4][4];
#pragma unroll
        for (int kf = 0; kf < 4; kf++) {
            uint32_t off = (uint32_t)((w * 16 + (mat & 1) * 8 + r) * 128)
                         + (uint32_t)((kf * 32 + (mat >> 1) * 16) ^ (r << 4));
            LDSM_X4(ah[kf][0], ah[kf][1], ah[kf][2], ah[kf][3], sb + off);
        }
        // kf-outer: same-accumulator ops 16 MMAs apart
#pragma unroll
        for (int kf = 0; kf < 4; kf++) {
            int krow = kf * 16 + (mat & 1) * 8 + r;
#pragma unroll
            for (int np = 0; np < 8; np++) {
                uint32_t bc = (uint32_t)(np * 32 + (mat >> 1) * 16);
                uint32_t off = (uint32_t)(krow * 256) + (bc & ~127u)
                             + ((bc & 127u) ^ (uint32_t)((krow & 7) << 4));
                uint32_t b0, b1, b2, b3;
                LDSM_X4T(b0, b1, b2, b3, sb + OFF_W + off);
                MMA_F16(acc[2 * np],     ah[kf][0], ah[kf][1], ah[kf][2], ah[kf][3], b0, b1);
                MMA_F16(acc[2 * np + 1], ah[kf][0], ah[kf][1], ah[kf][2], ah[kf][3], b2, b3);
            }
        }
    }

    const int row = r0 + w * 16 + g;
#pragma unroll
    for (int j = 0; j < 16; j++) {
        uint32_t p01 = pack_h2(acc[j][0], acc[j][1]);
        uint32_t p23 = pack_h2(acc[j][2], acc[j][3]);
        int col = j * 8 + q4 * 2;
        __half* dst = (col < 64) ? ko : vo;
        int cc = (col < 64) ? col : col - 64;
        *(uint32_t*)(dst + (size_t)row * 64 + cc)       = p01;
        *(uint32_t*)(dst + (size_t)(row + 8) * 64 + cc) = p23;
    }
}

// ---------------------------------------------------------------------------
// Attention (fp16) with fused Q projection (R16 structure; MMA nests
// reordered for independent-chain interleave).
// ---------------------------------------------------------------------------
__device__ __forceinline__ void issue_tile(
    uint32_t sb, uint32_t buf, int nt, int t,
    const uint4* k4, const uint4* v4)
{
    const uint4* k = k4 + nt * 1024;
    const uint4* v = v4 + nt * 1024;
#pragma unroll
    for (int i = t; i < 1024; i += 128) {
        int row = i >> 3, c = i & 7;
        uint32_t off = buf + (uint32_t)(row * 128)
                     + (uint32_t)((c * 16) ^ ((row & 7) << 4));
        CP_ASYNC16(sb + off,         k + i);
        CP_ASYNC16(sb + off + 16384, v + i);
    }
}

__global__ void __launch_bounds__(128, 2) attn_kernel(
    const float* __restrict__ X, const float* __restrict__ Wq,
    const __half* __restrict__ K, const __half* __restrict__ V,
    float* __restrict__ O)
{
    extern __shared__ char smem[];
    const uint32_t sb = smem_u32(smem);

    const int t    = threadIdx.x;
    const int w    = t >> 5, lane = t & 31;
    const int mw   = w >> 1, kw = w & 1;
    const int g    = lane >> 2, q4 = lane & 3;
    const int mat  = lane >> 3, r = lane & 7;
    const int bb   = blockIdx.y;
    const int m0   = blockIdx.x * 64;

    const uint4* k4 = (const uint4*)(K + (size_t)(bb * NDIM) * 64);
    const uint4* v4 = (const uint4*)(V + (size_t)(bb * NDIM) * 64);

    // ring tile 0 in flight during the whole prologue
    issue_tile(sb, 0, 0, t, k4, v4); CP_COMMIT();

    // ================= Q-projection prologue =================
    uint32_t qh[2][4][4];
    {
        constexpr uint32_t XA     = 32768;
        constexpr uint32_t XB     = 40960;
        constexpr uint32_t OFF_WQ = 49152;

        const float* Xb = X + (size_t)(bb * MDIM + m0) * DQK;

        auto stageX = [&](int kc, uint32_t dst) {
#pragma unroll
            for (int i = t; i < 1024; i += 128) {
                int row = i >> 4, c4 = i & 15;
                float4 v = *(const float4*)(Xb + (size_t)row * DQK + kc * 64 + c4 * 4);
                uint32_t h0 = pack_h2(v.x, v.y);
                uint32_t h1 = pack_h2(v.z, v.w);
                uint32_t off = (uint32_t)(row * 128)
                             + (uint32_t)((c4 * 8) ^ ((row & 7) << 4));
                *(uint2*)(smem + dst + off) = make_uint2(h0, h1);
            }
        };

#pragma unroll 4
        for (int i = t; i < 4096; i += 128) {
            int kr = i >> 4, c4 = i & 15;
            float4 v = *(const float4*)(Wq + (size_t)kr * 64 + c4 * 4);
            uint32_t h0 = pack_h2(v.x, v.y);
            uint32_t h1 = pack_h2(v.z, v.w);
            uint32_t bc = (uint32_t)(c4 * 8);
            uint32_t off = (uint32_t)(kr * 128) + (bc ^ (uint32_t)((kr & 7) << 4));
            *(uint2*)(smem + OFF_WQ + off) = make_uint2(h0, h1);
        }
        stageX(0, XA);
        __syncthreads();

        float qacc[2][8][4];
#pragma unroll
        for (int mt = 0; mt < 2; mt++)
#pragma unroll
            for (int j = 0; j < 8; j++)
#pragma unroll
                for (int i = 0; i < 4; i++) qacc[mt][j][i] = 0.f;

#pragma unroll
        for (int kc = 0; kc < 4; kc++) {
            if (kc < 3) stageX(kc + 1, (kc & 1) ? XA : XB);

            const uint32_t xs = (kc & 1) ? XB : XA;
            uint32_t ax[2][4][4];
#pragma unroll
            for (int mt = 0; mt < 2; mt++)
#pragma unroll
                for (int kf = 0; kf < 4; kf++) {
                    uint32_t off = (uint32_t)((mw * 32 + mt * 16 + (mat & 1) * 8 + r) * 128)
                                 + (uint32_t)((kf * 32 + (mat >> 1) * 16) ^ (r << 4));
                    LDSM_X4(ax[mt][kf][0], ax[mt][kf][1], ax[mt][kf][2], ax[mt][kf][3],
                            sb + xs + off);
                }
            // kf-outer: same-accumulator ops 16 MMAs apart
#pragma unroll
            for (int kf = 0; kf < 4; kf++) {
                int krow = kc * 64 + kf * 16 + (mat & 1) * 8 + r;
#pragma unroll
                for (int np = 0; np < 4; np++) {
                    uint32_t bc = (uint32_t)(np * 32 + (mat >> 1) * 16);
                    uint32_t off = (uint32_t)(krow * 128)
                                 + (bc ^ (uint32_t)((krow & 7) << 4));
                    uint32_t b0, b1, b2, b3;
                    LDSM_X4T(b0, b1, b2, b3, sb + OFF_WQ + off);
#pragma unroll
                    for (int mt = 0; mt < 2; mt++) {
                        MMA_F16(qacc[mt][2 * np],     ax[mt][kf][0], ax[mt][kf][1],
                                ax[mt][kf][2], ax[mt][kf][3], b0, b1);
                        MMA_F16(qacc[mt][2 * np + 1], ax[mt][kf][0], ax[mt][kf][1],
                                ax[mt][kf][2], ax[mt][kf][3], b2, b3);
                    }
                }
            }
            if (kc < 3) __syncthreads();
        }

        const float sc = 0.125f * LOG2E;
#pragma unroll
        for (int mt = 0; mt < 2; mt++)
#pragma unroll
            for (int kf = 0; kf < 4; kf++) {
                qh[mt][kf][0] = pack_h2(qacc[mt][2*kf][0] * sc,   qacc[mt][2*kf][1] * sc);
                qh[mt][kf][1] = pack_h2(qacc[mt][2*kf][2] * sc,   qacc[mt][2*kf][3] * sc);
                qh[mt][kf][2] = pack_h2(qacc[mt][2*kf+1][0] * sc, qacc[mt][2*kf+1][1] * sc);
                qh[mt][kf][3] = pack_h2(qacc[mt][2*kf+1][2] * sc, qacc[mt][2*kf+1][3] * sc);
            }
        __syncthreads();
    }
    issue_tile(sb, 32768, 1, t, k4, v4); CP_COMMIT();
    issue_tile(sb, 65536, 2, t, k4, v4); CP_COMMIT();
    // ================= end prologue =================

    float oacc[2][8][4];
#pragma unroll
    for (int mt = 0; mt < 2; mt++)
#pragma unroll
        for (int n = 0; n < 8; n++)
#pragma unroll
            for (int j = 0; j < 4; j++) oacc[mt][n][j] = 0.f;
    float ll[2][2] = {{0.f, 0.f}, {0.f, 0.f}};

    for (int nt = 0; nt < NDIM / 128; ++nt) {
        CP_WAIT2();
        __syncthreads();
        const uint32_t buf = (uint32_t)(nt % 3) * 32768u;

        uint32_t pa[2][4];
        uint32_t vb[4][4];

#pragma unroll
        for (int tp = 0; tp < 5; tp++) {
            if (tp > 0) {
                const int kgp = kw * 4 + tp - 1;
                const uint32_t rowa = (uint32_t)((kgp * 16 + (mat & 1) * 8 + r) * 128);
#pragma unroll
                for (int hp = 0; hp < 4; hp++) {
                    uint32_t av = sb + buf + 16384 + rowa
                                + (uint32_t)((hp * 32 + (mat >> 1) * 16) ^ (r << 4));
                    LDSM_X4T(vb[hp][0], vb[hp][1], vb[hp][2], vb[hp][3], av);
                }
            }

            uint32_t kb[4][4];
            if (tp < 4) {
                const int kg = kw * 4 + tp;
                const uint32_t rowb = (uint32_t)((kg * 16 + (mat >> 1) * 8 + r) * 128);
#pragma unroll
                for (int kf = 0; kf < 4; kf++) {
                    uint32_t a = sb + buf + rowb
                               + (uint32_t)((kf * 32 + (mat & 1) * 16) ^ (r << 4));
                    LDSM_X4(kb[kf][0], kb[kf][1], kb[kf][2], kb[kf][3], a);
                }
            }

            if (tp > 0) {
#pragma unroll
                for (int hp = 0; hp < 4; hp++)
#pragma unroll
                    for (int mt = 0; mt < 2; mt++) {
                        MMA_F16(oacc[mt][2 * hp],     pa[mt][0], pa[mt][1],
                                pa[mt][2], pa[mt][3], vb[hp][0], vb[hp][1]);
                        MMA_F16(oacc[mt][2 * hp + 1], pa[mt][0], pa[mt][1],
                                pa[mt][2], pa[mt][3], vb[hp][2], vb[hp][3]);
                    }
            }

            if (tp < 4) {
                float s[2][2][4];
#pragma unroll
                for (int mt = 0; mt < 2; mt++)
#pragma unroll
                    for (int nb = 0; nb < 2; nb++)
#pragma unroll
                        for (int j = 0; j < 4; j++) s[mt][nb][j] = 0.f;

                // kf-outer: 4 independent accumulator chains interleaved
#pragma unroll
                for (int kf = 0; kf < 4; kf++)
#pragma unroll
                    for (int mt = 0; mt < 2; mt++) {
                        MMA_F16(s[mt][0], qh[mt][kf][0], qh[mt][kf][1],
                                qh[mt][kf][2], qh[mt][kf][3], kb[kf][0], kb[kf][1]);
                        MMA_F16(s[mt][1], qh[mt][kf][0], qh[mt][kf][1],
                                qh[mt][kf][2], qh[mt][kf][3], kb[kf][2], kb[kf][3]);
                    }

#pragma unroll
                for (int mt = 0; mt < 2; mt++) {
                    float e00 = ex2f(s[mt][0][0]), e01 = ex2f(s[mt][0][1]);
                    float e02 = ex2f(s[mt][0][2]), e03 = ex2f(s[mt][0][3]);
                    float e10 = ex2f(s[mt][1][0]), e11 = ex2f(s[mt][1][1]);
                    float e12 = ex2f(s[mt][1][2]), e13 = ex2f(s[mt][1][3]);
                    ll[mt][0] += e00 + e01 + e10 + e11;
                    ll[mt][1] += e02 + e03 + e12 + e13;
                    pa[mt][0] = pack_h2(e00, e01); pa[mt][1] = pack_h2(e02, e03);
                    pa[mt][2] = pack_h2(e10, e11); pa[mt][3] = pack_h2(e12, e13);
                }
            }
        }

        __syncthreads();
        if (nt + 3 < NDIM / 128)
            issue_tile(sb, buf, nt + 3, t, k4, v4);
        CP_COMMIT();
    }

#pragma unroll
    for (int mt = 0; mt < 2; mt++)
#pragma unroll
        for (int h = 0; h < 2; h++) {
            ll[mt][h] += __shfl_xor_sync(0xffffffffu, ll[mt][h], 1);
            ll[mt][h] += __shfl_xor_sync(0xffffffffu, ll[mt][h], 2);
        }

    __syncthreads();
    float* Osm = (float*)smem;             // [64 rows][64 cols]
    float* lsm = (float*)(smem + 16384);   // [64 rows]

    if (kw == 1) {
#pragma unroll
        for (int mt = 0; mt < 2; mt++) {
            int rr = mw * 32 + mt * 16 + g;
            float* d0 = Osm + rr * 64;
            float* d1 = d0 + 8 * 64;
#pragma unroll
            for (int n = 0; n < 8; n++) {
                int col = n * 8 + q4 * 2;
                *(float2*)(d0 + col) = make_float2(oacc[mt][n][0], oacc[mt][n][1]);
                *(float2*)(d1 + col) = make_float2(oacc[mt][n][2], oacc[mt][n][3]);
            }
            if (q4 == 0) {
                lsm[rr]     = ll[mt][0];
                lsm[rr + 8] = ll[mt][1];
            }
        }
    }
    __syncthreads();

    if (kw == 0) {
#pragma unroll
        for (int mt = 0; mt < 2; mt++) {
            int rr = mw * 32 + mt * 16 + g;
            const float* s0 = Osm + rr * 64;
            const float* s1 = s0 + 8 * 64;
            const float i0 = 1.f / (ll[mt][0] + lsm[rr]);
            const float i1 = 1.f / (ll[mt][1] + lsm[rr + 8]);
            float* Og0 = O + ((size_t)(bb * MDIM + m0 + rr)) * 64;
            float* Og1 = Og0 + 8 * 64;
#pragma unroll
            for (int n = 0; n < 8; n++) {
                int col = n * 8 + q4 * 2;
                float2 a0 = *(const float2*)(s0 + col);
                float2 a1 = *(const float2*)(s1 + col);
                *(float2*)(Og0 + col) = make_float2((oacc[mt][n][0] + a0.x) * i0,
                                                    (oacc[mt][n][1] + a0.y) * i0);
                *(float2*)(Og1 + col) = make_float2((oacc[mt][n][2] + a1.x) * i1,
                                                    (oacc[mt][n][3] + a1.y) * i1);
            }
        }
    }
}

// ---------------------------------------------------------------------------
// Launch
// ---------------------------------------------------------------------------
extern "C" void kernel_launch(void* const* d_in, const int* in_sizes, int n_in,
                              void* d_out, int out_size)
{
    const float* x    = (const float*)d_in[0];
    const float* cond = (const float*)d_in[1];
    const float* Wq   = (const float*)d_in[2];
    const float* Wkv  = (const float*)d_in[3];
    float* out = (float*)d_out;

    __half *k, *v;
    cudaGetSymbolAddress((void**)&k, g_k);
    cudaGetSymbolAddress((void**)&v, g_v);

    cudaFuncSetAttribute(kv_proj,
                         cudaFuncAttributeMaxDynamicSharedMemorySize, 57344);
    cudaFuncSetAttribute(attn_kernel,
                         cudaFuncAttributeMaxDynamicSharedMemorySize, 98304);

    kv_proj<<<BATCH * NDIM / 64, 128, 57344>>>(cond, Wkv, k, v);

    dim3 grid(MDIM / 64, BATCH);
    attn_kernel<<<grid, 128, 98304>>>(x, Wq, k, v, out);
}